// round 10
// baseline (speedup 1.0000x reference)
#include <cuda_runtime.h>

// Problem constants
#define Bsz 128
#define Cch 64
#define Hh  32
#define Tt  256
#define BG  16   // batches per block
#define BAT 2    // batches per thread (reuse W registers across both)
#define IP  4    // hidden rows per thread
#define BOFF (Cch * Tt)   // element stride between consecutive batches
// threads = 2 dirs * (BG/BAT) * (Hh/IP) = 2*8*8 = 128 (4 warps)

typedef unsigned long long u64;

__device__ __forceinline__ u64 ffma2(u64 a, u64 b, u64 c) {
    u64 d;
    asm("fma.rn.f32x2 %0, %1, %2, %3;" : "=l"(d) : "l"(a), "l"(b), "l"(c));
    return d;
}
__device__ __forceinline__ u64 pack2(float lo, float hi) {
    u64 r;
    asm("mov.b64 %0, {%1, %2};" : "=l"(r) : "f"(lo), "f"(hi));
    return r;
}
__device__ __forceinline__ void unpack2(u64 v, float& lo, float& hi) {
    asm("mov.b64 {%0, %1}, %2;" : "=f"(lo), "=f"(hi) : "l"(v));
}

__global__ __launch_bounds__(128, 2)
void mrnn_kernel(const float* __restrict__ x,  const float* __restrict__ m,
                 const float* __restrict__ dd,
                 const float* __restrict__ Wf, const float* __restrict__ Vf,
                 const float* __restrict__ cf,
                 const float* __restrict__ Wb, const float* __restrict__ Vb,
                 const float* __restrict__ cb,
                 const float* __restrict__ U,  const float* __restrict__ c0,
                 float* __restrict__ out)
{
    // h state, double buffered: [buf][dir][b][40]  (stride 40 floats; each
    // quarter-warp phase of an LDS.128 is one 8-lane broadcast group)
    __shared__ __align__(16) float hbuf[2 * 2 * BG * 40];   // 10240 B
    // per-direction projection contributions: [dir][b][t]
    __shared__ float sfb[2 * BG * Tt];                       // 32768 B

    const int tid = threadIdx.x;
    const int g   = tid & 7;          // i-group (8 per (dir,b)) - intra-warp
    const int bp  = (tid >> 3) & 7;   // batch pair
    const int dir = tid >> 6;         // 0 = forward (warps 0-1), 1 = backward
    const int c   = blockIdx.y;
    const int b0  = blockIdx.x * BG;
    const int i0  = g * IP;
    const int ba  = 2 * bp;           // first batch of the pair

    // ---- preload per-thread weights into registers (shared by both batches) ----
    const float* Wg = (dir ? Wb : Wf) + c * Hh * Hh;
    const float* Vg = (dir ? Vb : Vf) + c * Hh * 3;
    const float* cg = (dir ? cb : cf) + c * Hh;

    u64   w[IP][16];                 // W rows, packed as (k even, k odd) pairs
    float v0[IP], v1[IP], v2[IP], cbi[IP], uu[IP];
    #pragma unroll
    for (int i = 0; i < IP; i++) {
        const u64* wr = (const u64*)(Wg + (i0 + i) * Hh);
        #pragma unroll
        for (int j = 0; j < 16; j++) w[i][j] = __ldg(wr + j);
        v0[i]  = __ldg(Vg + (i0 + i) * 3 + 0);
        v1[i]  = __ldg(Vg + (i0 + i) * 3 + 1);
        v2[i]  = __ldg(Vg + (i0 + i) * 3 + 2);
        cbi[i] = __ldg(cg + i0 + i);
        uu[i]  = __ldg(U + c * 2 * Hh + dir * Hh + i0 + i);
    }

    const long bc = (long)(b0 + ba) * Cch * Tt + (long)c * Tt;
    const float* xp = x  + bc;       // batch b: xp[tt + b*BOFF], b in {0,1}
    const float* mp = m  + bc;
    const float* dp = dd + bc;

    const int hrowA0 = (dir * BG + ba) * 40;            // batch a, buffer 0
    const int hrowA1 = (2 * BG + dir * BG + ba) * 40;   // batch a, buffer 1
    // batch b rows are +40 floats from batch a rows
    float* srowA = &sfb[(dir * BG + ba) * Tt];
    float* srowB = srowA + Tt;

    // zero own h rows (h0 = 0); intra-warp visibility only
    *(float4*)(&hbuf[hrowA0 + i0])      = make_float4(0.f, 0.f, 0.f, 0.f);
    *(float4*)(&hbuf[hrowA0 + 40 + i0]) = make_float4(0.f, 0.f, 0.f, 0.f);
    *(float4*)(&hbuf[hrowA1 + i0])      = make_float4(0.f, 0.f, 0.f, 0.f);
    *(float4*)(&hbuf[hrowA1 + 40 + i0]) = make_float4(0.f, 0.f, 0.f, 0.f);
    __syncwarp();

    // input for step n reads padded index: q = max(n-1,0), tt = dir ? T-1-q : q
    const int tt0 = dir ? (Tt - 1) : 0;
    float vxA = __ldg(xp + tt0),        vmA = __ldg(mp + tt0),        vdA = __ldg(dp + tt0);
    float vxB = __ldg(xp + BOFF + tt0), vmB = __ldg(mp + BOFF + tt0), vdB = __ldg(dp + BOFF + tt0);

    float sprevA = 0.f, sprevB = 0.f;  // deferred projection values
    int   tprev = 0;

    // ---- T sequential RNN steps (warp-independent: no block barrier) ----
    #pragma unroll 2
    for (int n = 0; n < Tt; n++) {
        // prefetch inputs for step n+1 (q_next = n; clamps naturally at n=T-1)
        // NOTE: ttn also equals this step's output time index tout.
        const int ttn = dir ? (Tt - 1 - n) : n;
        const float nvxA = __ldg(xp + ttn),        nvmA = __ldg(mp + ttn),        nvdA = __ldg(dp + ttn);
        const float nvxB = __ldg(xp + BOFF + ttn), nvmB = __ldg(mp + BOFF + ttn), nvdB = __ldg(dp + BOFF + ttn);

        const int rb = (n & 1) ? hrowA1 : hrowA0;
        const int wb = (n & 1) ? hrowA0 : hrowA1;
        const ulonglong2* hrA = (const ulonglong2*)&hbuf[rb];
        const ulonglong2* hrB = (const ulonglong2*)&hbuf[rb + 40];
        float*            hwA = &hbuf[wb];
        float*            hwB = &hbuf[wb + 40];

        // acc lane-lo seeded with bias + V*v; lane-hi accumulates odd-k terms
        u64 accA[IP], accB[IP];
        #pragma unroll
        for (int i = 0; i < IP; i++) {
            accA[i] = pack2(fmaf(v2[i], vdA, fmaf(v1[i], vmA, fmaf(v0[i], vxA, cbi[i]))), 0.f);
            accB[i] = pack2(fmaf(v2[i], vdB, fmaf(v1[i], vmB, fmaf(v0[i], vxB, cbi[i]))), 0.f);
        }

        // two 32x32 matvecs sharing W regs: 16 broadcast LDS.128 + 128 FFMA2
        #pragma unroll
        for (int j = 0; j < 8; j++) {
            const ulonglong2 hpA = hrA[j];
            const ulonglong2 hpB = hrB[j];
            #pragma unroll
            for (int i = 0; i < IP; i++) {
                accA[i] = ffma2(w[i][2 * j],     hpA.x, accA[i]);
                accA[i] = ffma2(w[i][2 * j + 1], hpA.y, accA[i]);
                accB[i] = ffma2(w[i][2 * j],     hpB.x, accB[i]);
                accB[i] = ffma2(w[i][2 * j + 1], hpB.y, accB[i]);
            }
        }

        float hnA[IP], hnB[IP];
        float sA = 0.f, sB = 0.f;
        #pragma unroll
        for (int i = 0; i < IP; i++) {
            float lo, hi;
            unpack2(accA[i], lo, hi);
            hnA[i] = fmaxf(lo + hi, 0.f);
            sA = fmaf(uu[i], hnA[i], sA);
            unpack2(accB[i], lo, hi);
            hnB[i] = fmaxf(lo + hi, 0.f);
            sB = fmaf(uu[i], hnB[i], sB);
        }

        *(float4*)(hwA + i0) = make_float4(hnA[0], hnA[1], hnA[2], hnA[3]);
        *(float4*)(hwB + i0) = make_float4(hnB[0], hnB[1], hnB[2], hnB[3]);

        __syncwarp();   // order hbuf STS before next step's LDS (intra-warp)

        // DEFERRED reduce of previous step's projections: overlaps the next
        // step's LDS/FMA stream instead of sitting on the recurrence path.
        if (n) {
            float rA = sprevA, rB = sprevB;
            rA += __shfl_xor_sync(0xffffffffu, rA, 1, 8);
            rB += __shfl_xor_sync(0xffffffffu, rB, 1, 8);
            rA += __shfl_xor_sync(0xffffffffu, rA, 2, 8);
            rB += __shfl_xor_sync(0xffffffffu, rB, 2, 8);
            rA += __shfl_xor_sync(0xffffffffu, rA, 4, 8);
            rB += __shfl_xor_sync(0xffffffffu, rB, 4, 8);
            if (g == 0) { srowA[tprev] = rA; srowB[tprev] = rB; }
        }
        sprevA = sA; sprevB = sB; tprev = ttn;

        vxA = nvxA; vmA = nvmA; vdA = nvdA;
        vxB = nvxB; vmB = nvmB; vdB = nvdB;
    }

    // tail: reduce + store the final step's projections
    {
        float rA = sprevA, rB = sprevB;
        rA += __shfl_xor_sync(0xffffffffu, rA, 1, 8);
        rB += __shfl_xor_sync(0xffffffffu, rB, 1, 8);
        rA += __shfl_xor_sync(0xffffffffu, rA, 2, 8);
        rB += __shfl_xor_sync(0xffffffffu, rB, 2, 8);
        rA += __shfl_xor_sync(0xffffffffu, rA, 4, 8);
        rB += __shfl_xor_sync(0xffffffffu, rB, 4, 8);
        if (g == 0) { srowA[tprev] = rA; srowB[tprev] = rB; }
    }

    __syncthreads();    // single block barrier: fwd+bwd sfb both complete

    // ---- combine fwd + bwd contributions, final relu, coalesced store ----
    const float c0c = __ldg(c0 + c);
    for (int idx = tid; idx < BG * Tt; idx += 128) {
        const int bb = idx >> 8;     // local batch
        const int t  = idx & 255;
        const float v = fmaxf(sfb[bb * Tt + t] + sfb[(BG + bb) * Tt + t] + c0c, 0.f);
        out[(long)(b0 + bb) * Cch * Tt + (long)c * Tt + t] = v;
    }
}

extern "C" void kernel_launch(void* const* d_in, const int* in_sizes, int n_in,
                              void* d_out, int out_size)
{
    const float* x  = (const float*)d_in[0];
    const float* m  = (const float*)d_in[1];
    const float* d  = (const float*)d_in[2];
    const float* Wf = (const float*)d_in[3];
    const float* Vf = (const float*)d_in[4];
    const float* cf = (const float*)d_in[5];
    const float* Wb = (const float*)d_in[6];
    const float* Vb = (const float*)d_in[7];
    const float* cb = (const float*)d_in[8];
    const float* U  = (const float*)d_in[9];
    const float* c0 = (const float*)d_in[10];

    dim3 grid(Bsz / BG, Cch);   // 8 x 64 = 512 blocks
    mrnn_kernel<<<grid, 128>>>(x, m, d, Wf, Vf, cf, Wb, Vb, cb, U, c0,
                               (float*)d_out);
}